// round 15
// baseline (speedup 1.0000x reference)
#include <cuda_runtime.h>
#include <cuda_bf16.h>

#define N_NODES_MAX 100000
#define N_EDGES_MAX 1600000
#define D_FEAT 64
#define SCAN_BLK 1024
#define MAX_SCAN_BLOCKS 128
#define K_MAX 5

// ---- scratch (allocation-free device globals) ------------------------------
__device__ float  g_y[K_MAX][N_NODES_MAX * D_FEAT];
__device__ int    g_offs[N_EDGES_MAX];               // CSR by dst: src byte offsets (src<<8)
__device__ int    g_rank[N_EDGES_MAX];               // rank of edge within its dst
__device__ int    g_rowstart[N_NODES_MAX + 1];
__device__ int    g_degi[N_NODES_MAX];
__device__ int    g_incl[N_NODES_MAX];
__device__ int    g_bsum[MAX_SCAN_BLOCKS];
__device__ float2 g_dfac[N_NODES_MAX];               // (1/deg, sqrt(deg))
__device__ float  g_dinv[N_NODES_MAX];               // 1/sqrt(deg)

// ---- degree count + rank capture: 4 edges/thread ------------------------------
__global__ void k_count_rank(const int* __restrict__ dst, int ne) {
    int i = blockIdx.x * blockDim.x + threadIdx.x;
    int e4 = ne >> 2;
    if (i < e4) {
        int4 d = reinterpret_cast<const int4*>(dst)[i];
        int4 r;
        r.x = atomicAdd(&g_degi[d.x], 1);
        r.y = atomicAdd(&g_degi[d.y], 1);
        r.z = atomicAdd(&g_degi[d.z], 1);
        r.w = atomicAdd(&g_degi[d.w], 1);
        reinterpret_cast<int4*>(g_rank)[i] = r;
    } else {
        int e = e4 * 4 + (i - e4);
        if (e < ne) g_rank[e] = atomicAdd(&g_degi[dst[e]], 1);
    }
}

// per-node factors + per-block EXCLUSIVE scan of degrees (warp-shuffle scan)
__global__ void k_dfac_scan1(int n) {
    __shared__ int wsum[32];
    int tid  = threadIdx.x;
    int lane = tid & 31;
    int wid  = tid >> 5;
    int i    = blockIdx.x * SCAN_BLK + tid;
    int deg  = (i < n) ? g_degi[i] : 0;
    if (i < n) {
        float dg  = fmaxf((float)deg, 1.0f);
        g_dinv[i] = rsqrtf(dg);
        g_dfac[i] = make_float2(1.0f / dg, sqrtf(dg));
    }
    int inc = deg;
#pragma unroll
    for (int off = 1; off < 32; off <<= 1) {
        int t = __shfl_up_sync(0xFFFFFFFFu, inc, off);
        if (lane >= off) inc += t;
    }
    if (lane == 31) wsum[wid] = inc;
    __syncthreads();
    if (wid == 0) {
        int w = wsum[lane];
        int wi = w;
#pragma unroll
        for (int off = 1; off < 32; off <<= 1) {
            int t = __shfl_up_sync(0xFFFFFFFFu, wi, off);
            if (lane >= off) wi += t;
        }
        wsum[lane] = wi - w;
    }
    __syncthreads();
    inc += wsum[wid];
    if (i < n) g_incl[i] = inc - deg;          // exclusive within block
    if (tid == SCAN_BLK - 1) g_bsum[blockIdx.x] = inc;
}

// merged scan2+scan3: add block offsets -> exclusive rowstart
__global__ void k_scan23(int n, int nb) {
    __shared__ int sh[MAX_SCAN_BLOCKS + 1];
    int tid = threadIdx.x;
    if (tid < 32) {
        int base = tid * 4;
        int v0 = (base + 0 < nb) ? g_bsum[base + 0] : 0;
        int v1 = (base + 1 < nb) ? g_bsum[base + 1] : 0;
        int v2 = (base + 2 < nb) ? g_bsum[base + 2] : 0;
        int v3 = (base + 3 < nb) ? g_bsum[base + 3] : 0;
        int s0 = v0, s1 = s0 + v1, s2 = s1 + v2, s3 = s2 + v3;
        int inc = s3;
#pragma unroll
        for (int off = 1; off < 32; off <<= 1) {
            int t = __shfl_up_sync(0xFFFFFFFFu, inc, off);
            if (tid >= off) inc += t;
        }
        int excl = inc - s3;
        sh[base + 0] = excl;
        sh[base + 1] = excl + s0;
        sh[base + 2] = excl + s1;
        sh[base + 3] = excl + s2;
        if (tid == 31) sh[MAX_SCAN_BLOCKS] = excl + s3;
    }
    __syncthreads();
    int i = blockIdx.x * SCAN_BLK + tid;
    if (i < n)
        g_rowstart[i] = g_incl[i] + sh[blockIdx.x];
    if (i == 0)
        g_rowstart[n] = sh[MAX_SCAN_BLOCKS];
}

// fused: atomic-free CSR fill (pos = rowstart[dst] + rank) + y0 = feat * dinv
__global__ void k_fill_init(const int* __restrict__ src,
                            const int* __restrict__ dst, int ne,
                            const float4* __restrict__ feat,
                            float4* __restrict__ y0, int n4) {
    int i = blockIdx.x * blockDim.x + threadIdx.x;
    int e4 = ne >> 2;
    if (i < e4) {
        int4 d = reinterpret_cast<const int4*>(dst)[i];
        int4 s = reinterpret_cast<const int4*>(src)[i];
        int4 r = reinterpret_cast<const int4*>(g_rank)[i];
        g_offs[__ldg(&g_rowstart[d.x]) + r.x] = s.x << 8;
        g_offs[__ldg(&g_rowstart[d.y]) + r.y] = s.y << 8;
        g_offs[__ldg(&g_rowstart[d.z]) + r.z] = s.z << 8;
        g_offs[__ldg(&g_rowstart[d.w]) + r.w] = s.w << 8;
    } else if (i < e4 + (ne & 3)) {
        int e = e4 * 4 + (i - e4);
        g_offs[__ldg(&g_rowstart[dst[e]]) + g_rank[e]] = src[e] << 8;
    }
    if (i < n4) {
        float di = g_dinv[i >> 4];
        float4 f = feat[i];
        y0[i] = make_float4(f.x * di, f.y * di, f.z * di, f.w * di);
    }
}

// ---- paired-edge gather core ---------------------------------------------------
// Lanes 0-15 cover edge 2p (16B each of its 256B row); lanes 16-31 cover edge 2p+1.
// Per edge-pair: 1 SHFL + 1 LDG.128 + 2 packed f32x2 adds.
// Returns full row sum as float4 (chunk q = lane&15) valid in ALL lanes.
__device__ __forceinline__ float4 gather_row_sum(const float* __restrict__ y_in,
                                                 int rs, int re, int lane) {
    int half = lane >> 4;         // 0: even edges, 1: odd edges
    int q    = lane & 15;         // 16B chunk index within row
    const char* base = reinterpret_cast<const char*>(y_in) + q * 16;

    unsigned long long a0 = 0ull, a1 = 0ull;

    int e = rs;
    while (e + 32 <= re) {
        int off_my = g_offs[e + lane];
#pragma unroll
        for (int p = 0; p < 16; p++) {
            int off = __shfl_sync(0xFFFFFFFFu, off_my, 2 * p + half);
            ulonglong2 v = *reinterpret_cast<const ulonglong2*>(base + off);
            asm("add.rn.f32x2 %0, %0, %1;" : "+l"(a0) : "l"(v.x));
            asm("add.rn.f32x2 %0, %0, %1;" : "+l"(a1) : "l"(v.y));
        }
        e += 32;
    }
    int cnt = re - e;
    if (cnt > 0) {
        int off_my = (lane < cnt) ? g_offs[e + lane] : 0;
        int pairs = cnt >> 1;
        for (int p = 0; p < pairs; p++) {
            int off = __shfl_sync(0xFFFFFFFFu, off_my, 2 * p + half);
            ulonglong2 v = *reinterpret_cast<const ulonglong2*>(base + off);
            asm("add.rn.f32x2 %0, %0, %1;" : "+l"(a0) : "l"(v.x));
            asm("add.rn.f32x2 %0, %0, %1;" : "+l"(a1) : "l"(v.y));
        }
        if (cnt & 1) {                       // lone last edge: half==0 lanes only
            int off = __shfl_sync(0xFFFFFFFFu, off_my, cnt - 1);
            if (half == 0) {
                ulonglong2 v = *reinterpret_cast<const ulonglong2*>(base + off);
                asm("add.rn.f32x2 %0, %0, %1;" : "+l"(a0) : "l"(v.x));
                asm("add.rn.f32x2 %0, %0, %1;" : "+l"(a1) : "l"(v.y));
            }
        }
    }

    float4 acc;
    acc.x = __uint_as_float((unsigned)(a0 & 0xFFFFFFFFull));
    acc.y = __uint_as_float((unsigned)(a0 >> 32));
    acc.z = __uint_as_float((unsigned)(a1 & 0xFFFFFFFFull));
    acc.w = __uint_as_float((unsigned)(a1 >> 32));

    // combine the two half-warps (same chunk q lives in lane and lane^16)
    acc.x += __shfl_xor_sync(0xFFFFFFFFu, acc.x, 16);
    acc.y += __shfl_xor_sync(0xFFFFFFFFu, acc.y, 16);
    acc.z += __shfl_xor_sync(0xFFFFFFFFu, acc.z, 16);
    acc.w += __shfl_xor_sync(0xFFFFFFFFu, acc.w, 16);
    return acc;
}

// ---- propagation round: one warp per node ------------------------------------
__global__ void __launch_bounds__(256)
k_round(const float* __restrict__ y_in,
        float* __restrict__ y_out,
        int n) {
    int gid  = blockIdx.x * blockDim.x + threadIdx.x;
    int d    = gid >> 5;
    int lane = gid & 31;
    if (d >= n) return;

    float4 acc = gather_row_sum(y_in, g_rowstart[d], g_rowstart[d + 1], lane);

    if (lane < 16) {                 // lanes 0-15 write the 256B row as float4s
        float invdeg = g_dfac[d].x;
        int t = d * 16 + lane;       // float4 index
        float4 yi = reinterpret_cast<const float4*>(y_in)[t];
        reinterpret_cast<float4*>(y_out)[t] =
            make_float4(yi.x - invdeg * acc.x,
                        yi.y - invdeg * acc.y,
                        yi.z - invdeg * acc.z,
                        yi.w - invdeg * acc.w);
    }
}

// ---- last round: epilogue writes h directly -----------------------------------
__global__ void __launch_bounds__(256)
k_round_last(const float* __restrict__ y_in,
             const float* __restrict__ feat,
             float* __restrict__ h,
             const float* __restrict__ theta,
             int K, int n) {
    int gid  = blockIdx.x * blockDim.x + threadIdx.x;
    int d    = gid >> 5;
    int lane = gid & 31;
    if (d >= n) return;

    float4 acc = gather_row_sum(y_in, g_rowstart[d], g_rowstart[d + 1], lane);

    if (lane < 16) {
        float2 dc = g_dfac[d];       // (1/deg, sqrt(deg))
        int t = d * 16 + lane;       // float4 index
        float4 yi = reinterpret_cast<const float4*>(y_in)[t];
        float4 yo = make_float4(yi.x - dc.x * acc.x,
                                yi.y - dc.x * acc.y,
                                yi.z - dc.x * acc.z,
                                yi.w - dc.x * acc.w);
        float sd = dc.y;
        float4 f = reinterpret_cast<const float4*>(feat)[t];
        float t0 = __ldg(&theta[0]);
        float4 hh = make_float4(t0 * f.x, t0 * f.y, t0 * f.z, t0 * f.w);
#pragma unroll
        for (int j = 1; j < K_MAX - 1; j++) {
            if (j >= K - 1) break;
            float ts = __ldg(&theta[j]) * sd;
            float4 y = reinterpret_cast<const float4*>(g_y[j])[t];
            hh.x += ts * y.x;
            hh.y += ts * y.y;
            hh.z += ts * y.z;
            hh.w += ts * y.w;
        }
        float tl = __ldg(&theta[K - 1]) * sd;
        hh.x += tl * yo.x;
        hh.y += tl * yo.y;
        hh.z += tl * yo.z;
        hh.w += tl * yo.w;
        reinterpret_cast<float4*>(h)[t] = hh;
    }
}

// guard path for K == 1
__global__ void k_theta0(const float4* __restrict__ feat, float* __restrict__ h,
                         const float* __restrict__ theta, int n4) {
    int t = blockIdx.x * blockDim.x + threadIdx.x;
    if (t >= n4) return;
    float t0 = __ldg(&theta[0]);
    float4 f = feat[t];
    reinterpret_cast<float4*>(h)[t] = make_float4(t0*f.x, t0*f.y, t0*f.z, t0*f.w);
}

// ---------------------------------------------------------------------------
extern "C" void kernel_launch(void* const* d_in, const int* in_sizes, int n_in,
                              void* d_out, int out_size) {
    const float* feat  = (const float*)d_in[0];
    const float* theta = (const float*)d_in[1];
    const int*   src   = (const int*)d_in[2];
    const int*   dst   = (const int*)d_in[3];
    float* h = (float*)d_out;

    const int n  = in_sizes[0] / D_FEAT;
    const int K  = in_sizes[1];
    const int ne = in_sizes[2];
    const int n4 = n * (D_FEAT / 4);

    const int T  = 256;
    const int nb = (n + SCAN_BLK - 1) / SCAN_BLK;

    if (K <= 1) {
        k_theta0<<<(n4 + T - 1) / T, T>>>(reinterpret_cast<const float4*>(feat),
                                          h, theta, n4);
        return;
    }

    void* degi_addr;
    cudaGetSymbolAddress(&degi_addr, g_degi);
    float* ybase;
    cudaGetSymbolAddress((void**)&ybase, g_y);
    const size_t ystride = (size_t)N_NODES_MAX * D_FEAT;

    // CSR build (R9 structure — proven fastest)
    cudaMemsetAsync(degi_addr, 0, (size_t)n * sizeof(int));
    int cd_threads = (ne >> 2) + (ne & 3);
    k_count_rank<<<(cd_threads + T - 1) / T, T>>>(dst, ne);
    k_dfac_scan1<<<nb, SCAN_BLK>>>(n);
    k_scan23<<<nb, SCAN_BLK>>>(n, nb);

    int mx = (cd_threads > n4) ? cd_threads : n4;
    k_fill_init<<<(mx + T - 1) / T, T>>>(src, dst, ne,
                                         reinterpret_cast<const float4*>(feat),
                                         reinterpret_cast<float4*>(ybase), n4);

    int gblocks = (n * 32 + T - 1) / T;
    for (int k = 1; k <= K - 2; k++) {
        k_round<<<gblocks, T>>>(ybase + (size_t)(k - 1) * ystride,
                                ybase + (size_t)k * ystride, n);
    }
    k_round_last<<<gblocks, T>>>(ybase + (size_t)(K - 2) * ystride,
                                 feat, h, theta, K, n);
}

// round 16
// speedup vs baseline: 1.2299x; 1.2299x over previous
#include <cuda_runtime.h>
#include <cuda_bf16.h>

#define N_NODES_MAX 100000
#define N_EDGES_MAX 1600000
#define D_FEAT 64
#define SCAN_BLK 1024
#define MAX_SCAN_BLOCKS 128
#define K_MAX 5

// ---- scratch (allocation-free device globals) ------------------------------
__device__ float  g_y[K_MAX][N_NODES_MAX * D_FEAT];
__device__ int    g_offs[N_EDGES_MAX];               // CSR by dst: src byte offsets (src<<8)
__device__ int    g_rank[N_EDGES_MAX];               // rank of edge within its dst
__device__ int    g_rowstart[N_NODES_MAX + 1];
__device__ int    g_degi[N_NODES_MAX];
__device__ int    g_incl[N_NODES_MAX];
__device__ int    g_bsum[MAX_SCAN_BLOCKS];
__device__ float2 g_dfac[N_NODES_MAX];               // (1/deg, sqrt(deg))
__device__ float  g_dinv[N_NODES_MAX];               // 1/sqrt(deg)

// ---- degree count + rank capture: 4 edges/thread ------------------------------
__global__ void k_count_rank(const int* __restrict__ dst, int ne) {
    int i = blockIdx.x * blockDim.x + threadIdx.x;
    int e4 = ne >> 2;
    if (i < e4) {
        int4 d = reinterpret_cast<const int4*>(dst)[i];
        int4 r;
        r.x = atomicAdd(&g_degi[d.x], 1);
        r.y = atomicAdd(&g_degi[d.y], 1);
        r.z = atomicAdd(&g_degi[d.z], 1);
        r.w = atomicAdd(&g_degi[d.w], 1);
        reinterpret_cast<int4*>(g_rank)[i] = r;
    } else {
        int e = e4 * 4 + (i - e4);
        if (e < ne) g_rank[e] = atomicAdd(&g_degi[dst[e]], 1);
    }
}

// per-node factors + per-block EXCLUSIVE scan of degrees (warp-shuffle scan)
__global__ void k_dfac_scan1(int n) {
    __shared__ int wsum[32];
    int tid  = threadIdx.x;
    int lane = tid & 31;
    int wid  = tid >> 5;
    int i    = blockIdx.x * SCAN_BLK + tid;
    int deg  = (i < n) ? g_degi[i] : 0;
    if (i < n) {
        float dg  = fmaxf((float)deg, 1.0f);
        g_dinv[i] = rsqrtf(dg);
        g_dfac[i] = make_float2(1.0f / dg, sqrtf(dg));
    }
    int inc = deg;
#pragma unroll
    for (int off = 1; off < 32; off <<= 1) {
        int t = __shfl_up_sync(0xFFFFFFFFu, inc, off);
        if (lane >= off) inc += t;
    }
    if (lane == 31) wsum[wid] = inc;
    __syncthreads();
    if (wid == 0) {
        int w = wsum[lane];
        int wi = w;
#pragma unroll
        for (int off = 1; off < 32; off <<= 1) {
            int t = __shfl_up_sync(0xFFFFFFFFu, wi, off);
            if (lane >= off) wi += t;
        }
        wsum[lane] = wi - w;
    }
    __syncthreads();
    inc += wsum[wid];
    if (i < n) g_incl[i] = inc - deg;          // exclusive within block
    if (tid == SCAN_BLK - 1) g_bsum[blockIdx.x] = inc;
}

// merged scan2+scan3: add block offsets -> exclusive rowstart
__global__ void k_scan23(int n, int nb) {
    __shared__ int sh[MAX_SCAN_BLOCKS + 1];
    int tid = threadIdx.x;
    if (tid < 32) {
        int base = tid * 4;
        int v0 = (base + 0 < nb) ? g_bsum[base + 0] : 0;
        int v1 = (base + 1 < nb) ? g_bsum[base + 1] : 0;
        int v2 = (base + 2 < nb) ? g_bsum[base + 2] : 0;
        int v3 = (base + 3 < nb) ? g_bsum[base + 3] : 0;
        int s0 = v0, s1 = s0 + v1, s2 = s1 + v2, s3 = s2 + v3;
        int inc = s3;
#pragma unroll
        for (int off = 1; off < 32; off <<= 1) {
            int t = __shfl_up_sync(0xFFFFFFFFu, inc, off);
            if (tid >= off) inc += t;
        }
        int excl = inc - s3;
        sh[base + 0] = excl;
        sh[base + 1] = excl + s0;
        sh[base + 2] = excl + s1;
        sh[base + 3] = excl + s2;
        if (tid == 31) sh[MAX_SCAN_BLOCKS] = excl + s3;
    }
    __syncthreads();
    int i = blockIdx.x * SCAN_BLK + tid;
    if (i < n)
        g_rowstart[i] = g_incl[i] + sh[blockIdx.x];
    if (i == 0)
        g_rowstart[n] = sh[MAX_SCAN_BLOCKS];
}

// fused: atomic-free CSR fill (pos = rowstart[dst] + rank) + y0 = feat * dinv
__global__ void k_fill_init(const int* __restrict__ src,
                            const int* __restrict__ dst, int ne,
                            const float4* __restrict__ feat,
                            float4* __restrict__ y0, int n4) {
    int i = blockIdx.x * blockDim.x + threadIdx.x;
    int e4 = ne >> 2;
    if (i < e4) {
        int4 d = reinterpret_cast<const int4*>(dst)[i];
        int4 s = reinterpret_cast<const int4*>(src)[i];
        int4 r = reinterpret_cast<const int4*>(g_rank)[i];
        g_offs[__ldg(&g_rowstart[d.x]) + r.x] = s.x << 8;
        g_offs[__ldg(&g_rowstart[d.y]) + r.y] = s.y << 8;
        g_offs[__ldg(&g_rowstart[d.z]) + r.z] = s.z << 8;
        g_offs[__ldg(&g_rowstart[d.w]) + r.w] = s.w << 8;
    } else if (i < e4 + (ne & 3)) {
        int e = e4 * 4 + (i - e4);
        g_offs[__ldg(&g_rowstart[dst[e]]) + g_rank[e]] = src[e] << 8;
    }
    if (i < n4) {
        float di = g_dinv[i >> 4];
        float4 f = feat[i];
        y0[i] = make_float4(f.x * di, f.y * di, f.z * di, f.w * di);
    }
}

// ---- gather core: one warp per node, lane owns 8B of the row -------------------
// Dual accumulators (even/odd edges) halve the FADD dependency chain.
__device__ __forceinline__ float2 gather_row_sum(const float* __restrict__ y_in,
                                                 int rs, int re, int lane) {
    const char* base = reinterpret_cast<const char*>(y_in) + lane * 8;
    unsigned long long a0 = 0ull, a1 = 0ull;

    int e = rs;
    while (e + 32 <= re) {
        int off_my = g_offs[e + lane];
#pragma unroll
        for (int j = 0; j < 32; j += 2) {
            int o0 = __shfl_sync(0xFFFFFFFFu, off_my, j);
            int o1 = __shfl_sync(0xFFFFFFFFu, off_my, j + 1);
            unsigned long long v0 = *reinterpret_cast<const unsigned long long*>(base + o0);
            unsigned long long v1 = *reinterpret_cast<const unsigned long long*>(base + o1);
            asm("add.rn.f32x2 %0, %0, %1;" : "+l"(a0) : "l"(v0));
            asm("add.rn.f32x2 %0, %0, %1;" : "+l"(a1) : "l"(v1));
        }
        e += 32;
    }
    int cnt = re - e;
    if (cnt > 0) {
        int off_my = (lane < cnt) ? g_offs[e + lane] : 0;
        int j = 0;
        for (; j + 4 <= cnt; j += 4) {
            int o0 = __shfl_sync(0xFFFFFFFFu, off_my, j + 0);
            int o1 = __shfl_sync(0xFFFFFFFFu, off_my, j + 1);
            int o2 = __shfl_sync(0xFFFFFFFFu, off_my, j + 2);
            int o3 = __shfl_sync(0xFFFFFFFFu, off_my, j + 3);
            unsigned long long v0 = *reinterpret_cast<const unsigned long long*>(base + o0);
            unsigned long long v1 = *reinterpret_cast<const unsigned long long*>(base + o1);
            unsigned long long v2 = *reinterpret_cast<const unsigned long long*>(base + o2);
            unsigned long long v3 = *reinterpret_cast<const unsigned long long*>(base + o3);
            asm("add.rn.f32x2 %0, %0, %1;" : "+l"(a0) : "l"(v0));
            asm("add.rn.f32x2 %0, %0, %1;" : "+l"(a1) : "l"(v1));
            asm("add.rn.f32x2 %0, %0, %1;" : "+l"(a0) : "l"(v2));
            asm("add.rn.f32x2 %0, %0, %1;" : "+l"(a1) : "l"(v3));
        }
        for (; j < cnt; j++) {
            int off = __shfl_sync(0xFFFFFFFFu, off_my, j);
            unsigned long long v = *reinterpret_cast<const unsigned long long*>(base + off);
            asm("add.rn.f32x2 %0, %0, %1;" : "+l"(a0) : "l"(v));
        }
    }

    // combine accumulators
    asm("add.rn.f32x2 %0, %0, %1;" : "+l"(a0) : "l"(a1));

    float2 acc;
    acc.x = __uint_as_float((unsigned)(a0 & 0xFFFFFFFFull));
    acc.y = __uint_as_float((unsigned)(a0 >> 32));
    return acc;
}

// ---- propagation round: one warp per node ------------------------------------
__global__ void __launch_bounds__(256)
k_round(const float* __restrict__ y_in,
        float* __restrict__ y_out,
        int n) {
    int gid  = blockIdx.x * blockDim.x + threadIdx.x;
    int d    = gid >> 5;
    int lane = gid & 31;
    if (d >= n) return;

    float2 acc = gather_row_sum(y_in, g_rowstart[d], g_rowstart[d + 1], lane);

    float invdeg = g_dfac[d].x;
    int t = d * 32 + lane;
    float2 yi = reinterpret_cast<const float2*>(y_in)[t];
    reinterpret_cast<float2*>(y_out)[t] =
        make_float2(yi.x - invdeg * acc.x, yi.y - invdeg * acc.y);
}

// ---- last round: epilogue writes h directly -----------------------------------
__global__ void __launch_bounds__(256)
k_round_last(const float* __restrict__ y_in,
             const float* __restrict__ feat,
             float* __restrict__ h,
             const float* __restrict__ theta,
             int K, int n) {
    int gid  = blockIdx.x * blockDim.x + threadIdx.x;
    int d    = gid >> 5;
    int lane = gid & 31;
    if (d >= n) return;

    float2 acc = gather_row_sum(y_in, g_rowstart[d], g_rowstart[d + 1], lane);

    float2 dc = g_dfac[d];
    int t = d * 32 + lane;
    float2 yi = reinterpret_cast<const float2*>(y_in)[t];
    float2 yo = make_float2(yi.x - dc.x * acc.x,
                            yi.y - dc.x * acc.y);

    float sd = dc.y;
    float2 f = reinterpret_cast<const float2*>(feat)[t];
    float t0 = __ldg(&theta[0]);
    float2 hh = make_float2(t0 * f.x, t0 * f.y);
#pragma unroll
    for (int j = 1; j < K_MAX - 1; j++) {
        if (j >= K - 1) break;
        float ts = __ldg(&theta[j]) * sd;
        float2 y = reinterpret_cast<const float2*>(g_y[j])[t];
        hh.x += ts * y.x;
        hh.y += ts * y.y;
    }
    float tl = __ldg(&theta[K - 1]) * sd;
    hh.x += tl * yo.x;
    hh.y += tl * yo.y;
    reinterpret_cast<float2*>(h)[t] = hh;
}

// guard path for K == 1
__global__ void k_theta0(const float4* __restrict__ feat, float* __restrict__ h,
                         const float* __restrict__ theta, int n4) {
    int t = blockIdx.x * blockDim.x + threadIdx.x;
    if (t >= n4) return;
    float t0 = __ldg(&theta[0]);
    float4 f = feat[t];
    reinterpret_cast<float4*>(h)[t] = make_float4(t0*f.x, t0*f.y, t0*f.z, t0*f.w);
}

// ---------------------------------------------------------------------------
extern "C" void kernel_launch(void* const* d_in, const int* in_sizes, int n_in,
                              void* d_out, int out_size) {
    const float* feat  = (const float*)d_in[0];
    const float* theta = (const float*)d_in[1];
    const int*   src   = (const int*)d_in[2];
    const int*   dst   = (const int*)d_in[3];
    float* h = (float*)d_out;

    const int n  = in_sizes[0] / D_FEAT;
    const int K  = in_sizes[1];
    const int ne = in_sizes[2];
    const int n4 = n * (D_FEAT / 4);

    const int T  = 256;
    const int nb = (n + SCAN_BLK - 1) / SCAN_BLK;

    if (K <= 1) {
        k_theta0<<<(n4 + T - 1) / T, T>>>(reinterpret_cast<const float4*>(feat),
                                          h, theta, n4);
        return;
    }

    void* degi_addr;
    cudaGetSymbolAddress(&degi_addr, g_degi);
    float* ybase;
    cudaGetSymbolAddress((void**)&ybase, g_y);
    const size_t ystride = (size_t)N_NODES_MAX * D_FEAT;

    // CSR build (R9 structure — proven fastest)
    cudaMemsetAsync(degi_addr, 0, (size_t)n * sizeof(int));
    int cd_threads = (ne >> 2) + (ne & 3);
    k_count_rank<<<(cd_threads + T - 1) / T, T>>>(dst, ne);
    k_dfac_scan1<<<nb, SCAN_BLK>>>(n);
    k_scan23<<<nb, SCAN_BLK>>>(n, nb);

    int mx = (cd_threads > n4) ? cd_threads : n4;
    k_fill_init<<<(mx + T - 1) / T, T>>>(src, dst, ne,
                                         reinterpret_cast<const float4*>(feat),
                                         reinterpret_cast<float4*>(ybase), n4);

    int gblocks = (n * 32 + T - 1) / T;
    for (int k = 1; k <= K - 2; k++) {
        k_round<<<gblocks, T>>>(ybase + (size_t)(k - 1) * ystride,
                                ybase + (size_t)k * ystride, n);
    }
    k_round_last<<<gblocks, T>>>(ybase + (size_t)(K - 2) * ystride,
                                 feat, h, theta, K, n);
}